// round 3
// baseline (speedup 1.0000x reference)
#include <cuda_runtime.h>
#include <cuda_fp16.h>
#include <cstdint>
#include <cstddef>

// ---------------------------------------------------------------------------
// Problem constants
// ---------------------------------------------------------------------------
#define TOK   16384      // total tokens = B*S = 8*2048
#define DDIM  1024
#define FDIM  4096
#define NPAIR 32         // MICRO_BATCHES * NUM_EXPERTS
#define TPP   512        // tokens per (mb, expert) pair -- contiguous rows
#define LN_EPS 1e-5f

#define BM 128
#define BN 128
#define KB 64            // halfs per K chunk (128 bytes/row)
#define TILE_BYTES 16384 // 128 rows * 128 bytes
#define NSTAGE 3
#define GEMM_SMEM (NSTAGE * 2 * TILE_BYTES + 1024)  // 99328

// ---------------------------------------------------------------------------
// Scratch (device globals: allocation-free rule)
// ---------------------------------------------------------------------------
__device__ __align__(1024) __half g_xh [(size_t)TOK * DDIM];          // LN(x) fp16
__device__ __align__(1024) __half g_w1t[(size_t)8 * FDIM * DDIM];     // w1^T fp16 [e][f][d]
__device__ __align__(1024) __half g_w2t[(size_t)8 * DDIM * FDIM];     // w2^T fp16 [e][d][f]
__device__ __align__(1024) __half g_h  [(size_t)TOK * FDIM];          // gelu(h) fp16

// ---------------------------------------------------------------------------
// Portable (non-"a") PTX helpers: cp.async, ldmatrix, mma.sync only
// ---------------------------------------------------------------------------
__device__ __forceinline__ uint32_t smem_u32(const void* p) {
    uint32_t a;
    asm("{ .reg .u64 t; cvta.to.shared.u64 t, %1; cvt.u32.u64 %0, t; }"
        : "=r"(a) : "l"(p));
    return a;
}

#define SMEM_SWZ128(o) ((o) ^ (((o) >> 3) & 0x70u))

#define CP_ASYNC16(sa, gp) \
    asm volatile("cp.async.cg.shared.global [%0], [%1], 16;\n" \
                 :: "r"(sa), "l"((const void*)(gp)) : "memory")
#define CP_COMMIT() asm volatile("cp.async.commit_group;\n" ::: "memory")
#define CP_WAIT_GROUP(n) \
    asm volatile("cp.async.wait_group %0;\n" :: "n"(n) : "memory")

#define LDSM_X4(r0, r1, r2, r3, addr) \
    asm volatile("ldmatrix.sync.aligned.m8n8.x4.shared.b16 {%0,%1,%2,%3}, [%4];" \
                 : "=r"(r0), "=r"(r1), "=r"(r2), "=r"(r3) : "r"(addr))

#define MMA16816(c, a0, a1, a2, a3, b0, b1) \
    asm volatile("mma.sync.aligned.m16n8k16.row.col.f32.f16.f16.f32 " \
                 "{%0,%1,%2,%3}, {%4,%5,%6,%7}, {%8,%9}, {%0,%1,%2,%3};" \
                 : "+f"((c)[0]), "+f"((c)[1]), "+f"((c)[2]), "+f"((c)[3]) \
                 : "r"(a0), "r"(a1), "r"(a2), "r"(a3), "r"(b0), "r"(b1))

__device__ __forceinline__ float gelu_exact(float x) {
    return 0.5f * x * (1.0f + erff(x * 0.70710678118654752440f));
}

// ---------------------------------------------------------------------------
// Kernel 1: LayerNorm -> fp16 scratch (one block per token)
// ---------------------------------------------------------------------------
__global__ void __launch_bounds__(256) ln_kernel(
    const float* __restrict__ x, const float* __restrict__ gamma,
    const float* __restrict__ beta)
{
    int t = threadIdx.x;
    size_t row = blockIdx.x;
    float4 v = reinterpret_cast<const float4*>(x + row * DDIM)[t];
    float s  = v.x + v.y + v.z + v.w;
    float ss = fmaf(v.x, v.x, fmaf(v.y, v.y, fmaf(v.z, v.z, v.w * v.w)));
#pragma unroll
    for (int o = 16; o; o >>= 1) {
        s  += __shfl_xor_sync(0xffffffffu, s, o);
        ss += __shfl_xor_sync(0xffffffffu, ss, o);
    }
    __shared__ float rs[8], rss[8];
    if ((t & 31) == 0) { rs[t >> 5] = s; rss[t >> 5] = ss; }
    __syncthreads();
    s = 0.f; ss = 0.f;
#pragma unroll
    for (int i = 0; i < 8; i++) { s += rs[i]; ss += rss[i]; }
    float mu   = s * (1.0f / DDIM);
    float var  = ss * (1.0f / DDIM) - mu * mu;
    float rstd = rsqrtf(var + LN_EPS);

    float4 gv = reinterpret_cast<const float4*>(gamma)[t];
    float4 bv = reinterpret_cast<const float4*>(beta)[t];
    float y0 = (v.x - mu) * rstd * gv.x + bv.x;
    float y1 = (v.y - mu) * rstd * gv.y + bv.y;
    float y2 = (v.z - mu) * rstd * gv.z + bv.z;
    float y3 = (v.w - mu) * rstd * gv.w + bv.w;
    __half2 h0 = __floats2half2_rn(y0, y1);
    __half2 h1 = __floats2half2_rn(y2, y3);
    uint2 u;
    u.x = *reinterpret_cast<uint32_t*>(&h0);
    u.y = *reinterpret_cast<uint32_t*>(&h1);
    reinterpret_cast<uint2*>(g_xh + row * DDIM)[t] = u;
}

// ---------------------------------------------------------------------------
// Kernels 2/3: fp32 weight transpose + fp16 convert (32x32 smem tiles)
// w1[e][d][f] -> g_w1t[e][f][d];  w2[e][f][d] -> g_w2t[e][d][f]
// ---------------------------------------------------------------------------
__global__ void __launch_bounds__(256) conv_w1_kernel(const float* __restrict__ w1)
{
    __shared__ float tile[32][33];
    int e = blockIdx.z, f0 = blockIdx.x << 5, d0 = blockIdx.y << 5;
    int tx = threadIdx.x, ty = threadIdx.y;
    const float* src = w1 + ((size_t)e * DDIM + d0) * FDIM + f0;
#pragma unroll
    for (int i = ty; i < 32; i += 8)
        tile[i][tx] = src[(size_t)i * FDIM + tx];         // (d0+i, f0+tx)
    __syncthreads();
    __half* dst = g_w1t + ((size_t)e * FDIM + f0) * DDIM + d0;
#pragma unroll
    for (int i = ty; i < 32; i += 8)
        dst[(size_t)i * DDIM + tx] = __float2half_rn(tile[tx][i]);  // (f0+i, d0+tx)
}

__global__ void __launch_bounds__(256) conv_w2_kernel(const float* __restrict__ w2)
{
    __shared__ float tile[32][33];
    int e = blockIdx.z, f0 = blockIdx.x << 5, d0 = blockIdx.y << 5;
    int tx = threadIdx.x, ty = threadIdx.y;
    const float* src = w2 + ((size_t)e * FDIM + f0) * DDIM + d0;
#pragma unroll
    for (int i = ty; i < 32; i += 8)
        tile[i][tx] = src[(size_t)i * DDIM + tx];         // (f0+i, d0+tx)
    __syncthreads();
    __half* dst = g_w2t + ((size_t)e * DDIM + d0) * FDIM + f0;
#pragma unroll
    for (int i = ty; i < 32; i += 8)
        dst[(size_t)i * FDIM + tx] = __float2half_rn(tile[tx][i]);  // (d0+i, f0+tx)
}

// ---------------------------------------------------------------------------
// Shared mainloop: C[128,128] += A[128,K] * B[128,K]^T, fp16 in / fp32 accum.
// 3-stage cp.async pipeline, SW128 XOR swizzle, ldmatrix + mma.sync.
// Warp grid 4(M) x 2(N); warp tile 32x64; accum c[2][8][4] per lane.
// ---------------------------------------------------------------------------
__device__ __forceinline__ void gemm_tile(
    uint32_t sA0, uint32_t sB0,
    const __half* __restrict__ A, int lda,
    const __half* __restrict__ B, int ldb,
    int NK, int tid, float c[2][8][4])
{
    const int lane = tid & 31, wid = tid >> 5;
    const int wm = wid & 3, wn = wid >> 2;

    // cp.async issue for K-chunk kc into stage st (whole CTA)
    auto issue = [&](int kc, int st) {
        const __half* Ag = A + (size_t)kc * KB;
        const __half* Bg = B + (size_t)kc * KB;
        uint32_t sa = sA0 + st * TILE_BYTES;
        uint32_t sbt = sB0 + st * TILE_BYTES;
#pragma unroll
        for (int i = 0; i < 4; i++) {
            int idx = tid + i * 256;
            int rr = idx >> 3, cc = idx & 7;
            uint32_t so = SMEM_SWZ128((uint32_t)(rr * 128 + cc * 16));
            CP_ASYNC16(sa + so,  Ag + (size_t)rr * lda + cc * 8);
            CP_ASYNC16(sbt + so, Bg + (size_t)rr * ldb + cc * 8);
        }
    };

    // per-lane ldmatrix addressing: row term + XOR mask (swizzle depends only
    // on row&7), column selector = (kt*32 | hi16) ^ mask
    const uint32_t colSel = (uint32_t)((lane >> 4) * 16);
    uint32_t aTerm[2], aMask[2], bTerm[4], bMask[4];
#pragma unroll
    for (int mt = 0; mt < 2; mt++) {
        int ar = wm * 32 + mt * 16 + (lane & 15);
        aTerm[mt] = (uint32_t)(ar * 128);
        aMask[mt] = (uint32_t)((ar & 7) * 16);
    }
#pragma unroll
    for (int nt2 = 0; nt2 < 4; nt2++) {
        int br = wn * 64 + nt2 * 16 + (lane & 15);
        bTerm[nt2] = (uint32_t)(br * 128);
        bMask[nt2] = (uint32_t)((br & 7) * 16);
    }

    issue(0, 0); CP_COMMIT();
    issue(1, 1); CP_COMMIT();

    for (int kc = 0; kc < NK; kc++) {
        CP_WAIT_GROUP(1);
        __syncthreads();
        if (kc + 2 < NK) {
            int st = kc + 2; st -= (st >= NSTAGE) ? NSTAGE : 0;
            if (st >= NSTAGE) st -= NSTAGE;
            issue(kc + 2, (kc + 2) % NSTAGE);
        }
        CP_COMMIT();

        int stage = kc % NSTAGE;
        uint32_t sa = sA0 + stage * TILE_BYTES;
        uint32_t sbt = sB0 + stage * TILE_BYTES;
#pragma unroll
        for (int kt = 0; kt < 4; kt++) {
            uint32_t kcol = (uint32_t)(kt * 32) | colSel;
            uint32_t a[2][4];
#pragma unroll
            for (int mt = 0; mt < 2; mt++) {
                uint32_t ad = sa + aTerm[mt] + (kcol ^ aMask[mt]);
                LDSM_X4(a[mt][0], a[mt][1], a[mt][2], a[mt][3], ad);
            }
#pragma unroll
            for (int nt2 = 0; nt2 < 4; nt2++) {
                uint32_t b0, b1, b2, b3;
                uint32_t bd = sbt + bTerm[nt2] + (kcol ^ bMask[nt2]);
                LDSM_X4(b0, b1, b2, b3, bd);
#pragma unroll
                for (int mt = 0; mt < 2; mt++) {
                    MMA16816(c[mt][nt2 * 2 + 0], a[mt][0], a[mt][1], a[mt][2], a[mt][3], b0, b2);
                    MMA16816(c[mt][nt2 * 2 + 1], a[mt][0], a[mt][1], a[mt][2], a[mt][3], b1, b3);
                }
            }
        }
    }
}

// ---------------------------------------------------------------------------
// Kernel 4: GEMM1 + bias + exact GELU -> g_h (fp16)
// grid = 32 pairs * 4 Mtiles * 32 Ntiles = 4096 blocks, 256 threads
// ---------------------------------------------------------------------------
__global__ void __launch_bounds__(256) gemm1_kernel(const float* __restrict__ b1)
{
    extern __shared__ char dsm[];
    uint32_t sb = (smem_u32(dsm) + 1023u) & ~1023u;
    int tid = threadIdx.x, bid = blockIdx.x;
    int pair = bid >> 7, mt4 = (bid >> 5) & 3, ntile = bid & 31, e = pair & 7;

    const __half* A = g_xh  + (size_t)(pair * TPP + mt4 * BM) * DDIM;
    const __half* B = g_w1t + ((size_t)e * FDIM + ntile * BN) * DDIM;

    float c[2][8][4];
#pragma unroll
    for (int i = 0; i < 2; i++)
#pragma unroll
        for (int j = 0; j < 8; j++)
#pragma unroll
            for (int k = 0; k < 4; k++) c[i][j][k] = 0.f;

    gemm_tile(sb, sb + NSTAGE * TILE_BYTES, A, DDIM, B, DDIM, DDIM / KB, tid, c);

    int lane = tid & 31, wid = tid >> 5, wm = wid & 3, wn = wid >> 2;
    int rowBase = pair * TPP + mt4 * BM + wm * 32 + (lane >> 2);
    int colBase = ntile * BN + wn * 64 + (lane & 3) * 2;
    const float* b1e = b1 + (size_t)e * FDIM;
#pragma unroll
    for (int mt = 0; mt < 2; mt++) {
#pragma unroll
        for (int nt = 0; nt < 8; nt++) {
            int row = rowBase + mt * 16;
            int col = colBase + nt * 8;
            float2 bb = *reinterpret_cast<const float2*>(b1e + col);
            __half2 h0 = __floats2half2_rn(gelu_exact(c[mt][nt][0] + bb.x),
                                           gelu_exact(c[mt][nt][1] + bb.y));
            __half2 h1 = __floats2half2_rn(gelu_exact(c[mt][nt][2] + bb.x),
                                           gelu_exact(c[mt][nt][3] + bb.y));
            *reinterpret_cast<__half2*>(g_h + (size_t)row * FDIM + col) = h0;
            *reinterpret_cast<__half2*>(g_h + (size_t)(row + 8) * FDIM + col) = h1;
        }
    }
}

// ---------------------------------------------------------------------------
// Kernel 5: GEMM2 + bias + residual -> out (fp32)
// grid = 32 pairs * 4 Mtiles * 8 Ntiles = 1024 blocks, 256 threads
// ---------------------------------------------------------------------------
__global__ void __launch_bounds__(256) gemm2_kernel(
    const float* __restrict__ b2, const float* __restrict__ x,
    float* __restrict__ out)
{
    extern __shared__ char dsm[];
    uint32_t sb = (smem_u32(dsm) + 1023u) & ~1023u;
    int tid = threadIdx.x, bid = blockIdx.x;
    int pair = bid >> 5, mt4 = (bid >> 3) & 3, ntile = bid & 7, e = pair & 7;

    const __half* A = g_h   + (size_t)(pair * TPP + mt4 * BM) * FDIM;
    const __half* B = g_w2t + ((size_t)e * DDIM + ntile * BN) * FDIM;

    float c[2][8][4];
#pragma unroll
    for (int i = 0; i < 2; i++)
#pragma unroll
        for (int j = 0; j < 8; j++)
#pragma unroll
            for (int k = 0; k < 4; k++) c[i][j][k] = 0.f;

    gemm_tile(sb, sb + NSTAGE * TILE_BYTES, A, FDIM, B, FDIM, FDIM / KB, tid, c);

    int lane = tid & 31, wid = tid >> 5, wm = wid & 3, wn = wid >> 2;
    int rowBase = pair * TPP + mt4 * BM + wm * 32 + (lane >> 2);
    int colBase = ntile * BN + wn * 64 + (lane & 3) * 2;
    const float* b2e = b2 + (size_t)e * DDIM;
#pragma unroll
    for (int mt = 0; mt < 2; mt++) {
#pragma unroll
        for (int nt = 0; nt < 8; nt++) {
            int row = rowBase + mt * 16;
            int col = colBase + nt * 8;
            float2 bb = *reinterpret_cast<const float2*>(b2e + col);
            float2 x0 = *reinterpret_cast<const float2*>(x + (size_t)row * DDIM + col);
            float2 x1 = *reinterpret_cast<const float2*>(x + (size_t)(row + 8) * DDIM + col);
            float2 o0, o1;
            o0.x = c[mt][nt][0] + bb.x + x0.x;
            o0.y = c[mt][nt][1] + bb.y + x0.y;
            o1.x = c[mt][nt][2] + bb.x + x1.x;
            o1.y = c[mt][nt][3] + bb.y + x1.y;
            *reinterpret_cast<float2*>(out + (size_t)row * DDIM + col) = o0;
            *reinterpret_cast<float2*>(out + (size_t)(row + 8) * DDIM + col) = o1;
        }
    }
}

// ---------------------------------------------------------------------------
// Launch
// inputs: x, gamma, beta, gate_w(unused), w1, b1, w2, b2 ; out fp32
// ---------------------------------------------------------------------------
extern "C" void kernel_launch(void* const* d_in, const int* in_sizes, int n_in,
                              void* d_out, int out_size)
{
    const float* x     = (const float*)d_in[0];
    const float* gamma = (const float*)d_in[1];
    const float* beta  = (const float*)d_in[2];
    const float* w1    = (const float*)d_in[4];
    const float* b1    = (const float*)d_in[5];
    const float* w2    = (const float*)d_in[6];
    const float* b2    = (const float*)d_in[7];
    float* out = (float*)d_out;

    cudaFuncSetAttribute(gemm1_kernel, cudaFuncAttributeMaxDynamicSharedMemorySize, GEMM_SMEM);
    cudaFuncSetAttribute(gemm2_kernel, cudaFuncAttributeMaxDynamicSharedMemorySize, GEMM_SMEM);

    ln_kernel<<<TOK, 256>>>(x, gamma, beta);
    conv_w1_kernel<<<dim3(FDIM / 32, DDIM / 32, 8), dim3(32, 8)>>>(w1);
    conv_w2_kernel<<<dim3(FDIM / 32, DDIM / 32, 8), dim3(32, 8)>>>(w2);
    gemm1_kernel<<<NPAIR * 4 * (FDIM / BN), 256, GEMM_SMEM>>>(b1);
    gemm2_kernel<<<NPAIR * 4 * (DDIM / BN), 256, GEMM_SMEM>>>(b2, x, out);
}

// round 4
// speedup vs baseline: 1.0021x; 1.0021x over previous
#include <cuda_runtime.h>
#include <cuda_fp16.h>
#include <cstdint>
#include <cstddef>

// ---------------------------------------------------------------------------
// Problem constants
// ---------------------------------------------------------------------------
#define TOK   16384      // total tokens = B*S = 8*2048
#define DDIM  1024
#define FDIM  4096
#define NPAIR 32         // MICRO_BATCHES * NUM_EXPERTS
#define TPP   512        // tokens per (mb, expert) pair -- contiguous rows
#define LN_EPS 1e-5f

#define BM 128
#define BN 128
#define KB 64            // halfs per K chunk (128 bytes/row)
#define TILE_BYTES 16384 // 128 rows * 128 bytes
#define NSTAGE 3
#define GEMM_SMEM (NSTAGE * 2 * TILE_BYTES + 1024)  // 99328

// ---------------------------------------------------------------------------
// Scratch (device globals: allocation-free rule)
// ---------------------------------------------------------------------------
__device__ __align__(1024) __half g_xh [(size_t)TOK * DDIM];          // LN(x) fp16
__device__ __align__(1024) __half g_w1t[(size_t)8 * FDIM * DDIM];     // w1^T fp16 [e][f][d]
__device__ __align__(1024) __half g_w2t[(size_t)8 * DDIM * FDIM];     // w2^T fp16 [e][d][f]
__device__ __align__(1024) __half g_h  [(size_t)TOK * FDIM];          // gelu(h) fp16

// ---------------------------------------------------------------------------
// Portable (non-"a") PTX helpers: cp.async, ldmatrix, mma.sync only
// ---------------------------------------------------------------------------
__device__ __forceinline__ uint32_t smem_u32(const void* p) {
    uint32_t a;
    asm("{ .reg .u64 t; cvta.to.shared.u64 t, %1; cvt.u32.u64 %0, t; }"
        : "=r"(a) : "l"(p));
    return a;
}

#define SMEM_SWZ128(o) ((o) ^ (((o) >> 3) & 0x70u))

#define CP_ASYNC16(sa, gp) \
    asm volatile("cp.async.cg.shared.global [%0], [%1], 16;\n" \
                 :: "r"(sa), "l"((const void*)(gp)) : "memory")
#define CP_COMMIT() asm volatile("cp.async.commit_group;\n" ::: "memory")
#define CP_WAIT_GROUP(n) \
    asm volatile("cp.async.wait_group %0;\n" :: "n"(n) : "memory")

#define LDSM_X4(r0, r1, r2, r3, addr) \
    asm volatile("ldmatrix.sync.aligned.m8n8.x4.shared.b16 {%0,%1,%2,%3}, [%4];" \
                 : "=r"(r0), "=r"(r1), "=r"(r2), "=r"(r3) : "r"(addr))

#define MMA16816(c, a0, a1, a2, a3, b0, b1) \
    asm volatile("mma.sync.aligned.m16n8k16.row.col.f32.f16.f16.f32 " \
                 "{%0,%1,%2,%3}, {%4,%5,%6,%7}, {%8,%9}, {%0,%1,%2,%3};" \
                 : "+f"((c)[0]), "+f"((c)[1]), "+f"((c)[2]), "+f"((c)[3]) \
                 : "r"(a0), "r"(a1), "r"(a2), "r"(a3), "r"(b0), "r"(b1))

__device__ __forceinline__ float gelu_exact(float x) {
    return 0.5f * x * (1.0f + erff(x * 0.70710678118654752440f));
}

// ---------------------------------------------------------------------------
// Kernel 1: LayerNorm -> fp16 scratch (one block per token)
// ---------------------------------------------------------------------------
__global__ void __launch_bounds__(256) ln_kernel(
    const float* __restrict__ x, const float* __restrict__ gamma,
    const float* __restrict__ beta)
{
    int t = threadIdx.x;
    size_t row = blockIdx.x;
    float4 v = reinterpret_cast<const float4*>(x + row * DDIM)[t];
    float s  = v.x + v.y + v.z + v.w;
    float ss = fmaf(v.x, v.x, fmaf(v.y, v.y, fmaf(v.z, v.z, v.w * v.w)));
#pragma unroll
    for (int o = 16; o; o >>= 1) {
        s  += __shfl_xor_sync(0xffffffffu, s, o);
        ss += __shfl_xor_sync(0xffffffffu, ss, o);
    }
    __shared__ float rs[8], rss[8];
    if ((t & 31) == 0) { rs[t >> 5] = s; rss[t >> 5] = ss; }
    __syncthreads();
    s = 0.f; ss = 0.f;
#pragma unroll
    for (int i = 0; i < 8; i++) { s += rs[i]; ss += rss[i]; }
    float mu   = s * (1.0f / DDIM);
    float var  = ss * (1.0f / DDIM) - mu * mu;
    float rstd = rsqrtf(var + LN_EPS);

    float4 gv = reinterpret_cast<const float4*>(gamma)[t];
    float4 bv = reinterpret_cast<const float4*>(beta)[t];
    float y0 = (v.x - mu) * rstd * gv.x + bv.x;
    float y1 = (v.y - mu) * rstd * gv.y + bv.y;
    float y2 = (v.z - mu) * rstd * gv.z + bv.z;
    float y3 = (v.w - mu) * rstd * gv.w + bv.w;
    __half2 h0 = __floats2half2_rn(y0, y1);
    __half2 h1 = __floats2half2_rn(y2, y3);
    uint2 u;
    u.x = *reinterpret_cast<uint32_t*>(&h0);
    u.y = *reinterpret_cast<uint32_t*>(&h1);
    reinterpret_cast<uint2*>(g_xh + row * DDIM)[t] = u;
}

// ---------------------------------------------------------------------------
// Kernels 2/3: fp32 weight transpose + fp16 convert (32x32 smem tiles)
// w1[e][d][f] -> g_w1t[e][f][d];  w2[e][f][d] -> g_w2t[e][d][f]
// ---------------------------------------------------------------------------
__global__ void __launch_bounds__(256) conv_w1_kernel(const float* __restrict__ w1)
{
    __shared__ float tile[32][33];
    int e = blockIdx.z, f0 = blockIdx.x << 5, d0 = blockIdx.y << 5;
    int tx = threadIdx.x, ty = threadIdx.y;
    const float* src = w1 + ((size_t)e * DDIM + d0) * FDIM + f0;
#pragma unroll
    for (int i = ty; i < 32; i += 8)
        tile[i][tx] = src[(size_t)i * FDIM + tx];         // (d0+i, f0+tx)
    __syncthreads();
    __half* dst = g_w1t + ((size_t)e * FDIM + f0) * DDIM + d0;
#pragma unroll
    for (int i = ty; i < 32; i += 8)
        dst[(size_t)i * DDIM + tx] = __float2half_rn(tile[tx][i]);  // (f0+i, d0+tx)
}

__global__ void __launch_bounds__(256) conv_w2_kernel(const float* __restrict__ w2)
{
    __shared__ float tile[32][33];
    int e = blockIdx.z, f0 = blockIdx.x << 5, d0 = blockIdx.y << 5;
    int tx = threadIdx.x, ty = threadIdx.y;
    const float* src = w2 + ((size_t)e * FDIM + f0) * DDIM + d0;
#pragma unroll
    for (int i = ty; i < 32; i += 8)
        tile[i][tx] = src[(size_t)i * DDIM + tx];         // (f0+i, d0+tx)
    __syncthreads();
    __half* dst = g_w2t + ((size_t)e * DDIM + d0) * FDIM + f0;
#pragma unroll
    for (int i = ty; i < 32; i += 8)
        dst[(size_t)i * FDIM + tx] = __float2half_rn(tile[tx][i]);  // (d0+i, f0+tx)
}

// ---------------------------------------------------------------------------
// Shared mainloop: C[128,128] += A[128,K] * B[128,K]^T, fp16 in / fp32 accum.
// 3-stage cp.async pipeline, SW128 XOR swizzle, ldmatrix + mma.sync.
// Warp grid 4(M) x 2(N); warp tile 32x64; accum c[2][8][4] per lane.
// ---------------------------------------------------------------------------
__device__ __forceinline__ void gemm_tile(
    uint32_t sA0, uint32_t sB0,
    const __half* __restrict__ A, int lda,
    const __half* __restrict__ B, int ldb,
    int NK, int tid, float c[2][8][4])
{
    const int lane = tid & 31, wid = tid >> 5;
    const int wm = wid & 3, wn = wid >> 2;

    // cp.async issue for K-chunk kc into stage st (whole CTA)
    auto issue = [&](int kc, int st) {
        const __half* Ag = A + (size_t)kc * KB;
        const __half* Bg = B + (size_t)kc * KB;
        uint32_t sa = sA0 + st * TILE_BYTES;
        uint32_t sbt = sB0 + st * TILE_BYTES;
#pragma unroll
        for (int i = 0; i < 4; i++) {
            int idx = tid + i * 256;
            int rr = idx >> 3, cc = idx & 7;
            uint32_t so = SMEM_SWZ128((uint32_t)(rr * 128 + cc * 16));
            CP_ASYNC16(sa + so,  Ag + (size_t)rr * lda + cc * 8);
            CP_ASYNC16(sbt + so, Bg + (size_t)rr * ldb + cc * 8);
        }
    };

    // per-lane ldmatrix addressing: row term + XOR mask (swizzle depends only
    // on row&7), column selector = (kt*32 | hi16) ^ mask
    const uint32_t colSel = (uint32_t)((lane >> 4) * 16);
    uint32_t aTerm[2], aMask[2], bTerm[4], bMask[4];
#pragma unroll
    for (int mt = 0; mt < 2; mt++) {
        int ar = wm * 32 + mt * 16 + (lane & 15);
        aTerm[mt] = (uint32_t)(ar * 128);
        aMask[mt] = (uint32_t)((ar & 7) * 16);
    }
#pragma unroll
    for (int nt2 = 0; nt2 < 4; nt2++) {
        int br = wn * 64 + nt2 * 16 + (lane & 15);
        bTerm[nt2] = (uint32_t)(br * 128);
        bMask[nt2] = (uint32_t)((br & 7) * 16);
    }

    issue(0, 0); CP_COMMIT();
    issue(1, 1); CP_COMMIT();

    for (int kc = 0; kc < NK; kc++) {
        CP_WAIT_GROUP(1);
        __syncthreads();
        if (kc + 2 < NK) {
            int st = kc + 2; st -= (st >= NSTAGE) ? NSTAGE : 0;
            if (st >= NSTAGE) st -= NSTAGE;
            issue(kc + 2, (kc + 2) % NSTAGE);
        }
        CP_COMMIT();

        int stage = kc % NSTAGE;
        uint32_t sa = sA0 + stage * TILE_BYTES;
        uint32_t sbt = sB0 + stage * TILE_BYTES;
#pragma unroll
        for (int kt = 0; kt < 4; kt++) {
            uint32_t kcol = (uint32_t)(kt * 32) | colSel;
            uint32_t a[2][4];
#pragma unroll
            for (int mt = 0; mt < 2; mt++) {
                uint32_t ad = sa + aTerm[mt] + (kcol ^ aMask[mt]);
                LDSM_X4(a[mt][0], a[mt][1], a[mt][2], a[mt][3], ad);
            }
#pragma unroll
            for (int nt2 = 0; nt2 < 4; nt2++) {
                uint32_t b0, b1, b2, b3;
                uint32_t bd = sbt + bTerm[nt2] + (kcol ^ bMask[nt2]);
                LDSM_X4(b0, b1, b2, b3, bd);
#pragma unroll
                for (int mt = 0; mt < 2; mt++) {
                    MMA16816(c[mt][nt2 * 2 + 0], a[mt][0], a[mt][1], a[mt][2], a[mt][3], b0, b2);
                    MMA16816(c[mt][nt2 * 2 + 1], a[mt][0], a[mt][1], a[mt][2], a[mt][3], b1, b3);
                }
            }
        }
    }
}

// ---------------------------------------------------------------------------
// Kernel 4: GEMM1 + bias + exact GELU -> g_h (fp16)
// grid = 32 pairs * 4 Mtiles * 32 Ntiles = 4096 blocks, 256 threads
// ---------------------------------------------------------------------------
__global__ void __launch_bounds__(256) gemm1_kernel(const float* __restrict__ b1)
{
    extern __shared__ char dsm[];
    uint32_t sb = (smem_u32(dsm) + 1023u) & ~1023u;
    int tid = threadIdx.x, bid = blockIdx.x;
    int pair = bid >> 7, mt4 = (bid >> 5) & 3, ntile = bid & 31, e = pair & 7;

    const __half* A = g_xh  + (size_t)(pair * TPP + mt4 * BM) * DDIM;
    const __half* B = g_w1t + ((size_t)e * FDIM + ntile * BN) * DDIM;

    float c[2][8][4];
#pragma unroll
    for (int i = 0; i < 2; i++)
#pragma unroll
        for (int j = 0; j < 8; j++)
#pragma unroll
            for (int k = 0; k < 4; k++) c[i][j][k] = 0.f;

    gemm_tile(sb, sb + NSTAGE * TILE_BYTES, A, DDIM, B, DDIM, DDIM / KB, tid, c);

    int lane = tid & 31, wid = tid >> 5, wm = wid & 3, wn = wid >> 2;
    int rowBase = pair * TPP + mt4 * BM + wm * 32 + (lane >> 2);
    int colBase = ntile * BN + wn * 64 + (lane & 3) * 2;
    const float* b1e = b1 + (size_t)e * FDIM;
#pragma unroll
    for (int mt = 0; mt < 2; mt++) {
#pragma unroll
        for (int nt = 0; nt < 8; nt++) {
            int row = rowBase + mt * 16;
            int col = colBase + nt * 8;
            float2 bb = *reinterpret_cast<const float2*>(b1e + col);
            __half2 h0 = __floats2half2_rn(gelu_exact(c[mt][nt][0] + bb.x),
                                           gelu_exact(c[mt][nt][1] + bb.y));
            __half2 h1 = __floats2half2_rn(gelu_exact(c[mt][nt][2] + bb.x),
                                           gelu_exact(c[mt][nt][3] + bb.y));
            *reinterpret_cast<__half2*>(g_h + (size_t)row * FDIM + col) = h0;
            *reinterpret_cast<__half2*>(g_h + (size_t)(row + 8) * FDIM + col) = h1;
        }
    }
}

// ---------------------------------------------------------------------------
// Kernel 5: GEMM2 + bias + residual -> out (fp32)
// grid = 32 pairs * 4 Mtiles * 8 Ntiles = 1024 blocks, 256 threads
// ---------------------------------------------------------------------------
__global__ void __launch_bounds__(256) gemm2_kernel(
    const float* __restrict__ b2, const float* __restrict__ x,
    float* __restrict__ out)
{
    extern __shared__ char dsm[];
    uint32_t sb = (smem_u32(dsm) + 1023u) & ~1023u;
    int tid = threadIdx.x, bid = blockIdx.x;
    int pair = bid >> 5, mt4 = (bid >> 3) & 3, ntile = bid & 7, e = pair & 7;

    const __half* A = g_h   + (size_t)(pair * TPP + mt4 * BM) * FDIM;
    const __half* B = g_w2t + ((size_t)e * DDIM + ntile * BN) * FDIM;

    float c[2][8][4];
#pragma unroll
    for (int i = 0; i < 2; i++)
#pragma unroll
        for (int j = 0; j < 8; j++)
#pragma unroll
            for (int k = 0; k < 4; k++) c[i][j][k] = 0.f;

    gemm_tile(sb, sb + NSTAGE * TILE_BYTES, A, FDIM, B, FDIM, FDIM / KB, tid, c);

    int lane = tid & 31, wid = tid >> 5, wm = wid & 3, wn = wid >> 2;
    int rowBase = pair * TPP + mt4 * BM + wm * 32 + (lane >> 2);
    int colBase = ntile * BN + wn * 64 + (lane & 3) * 2;
    const float* b2e = b2 + (size_t)e * DDIM;
#pragma unroll
    for (int mt = 0; mt < 2; mt++) {
#pragma unroll
        for (int nt = 0; nt < 8; nt++) {
            int row = rowBase + mt * 16;
            int col = colBase + nt * 8;
            float2 bb = *reinterpret_cast<const float2*>(b2e + col);
            float2 x0 = *reinterpret_cast<const float2*>(x + (size_t)row * DDIM + col);
            float2 x1 = *reinterpret_cast<const float2*>(x + (size_t)(row + 8) * DDIM + col);
            float2 o0, o1;
            o0.x = c[mt][nt][0] + bb.x + x0.x;
            o0.y = c[mt][nt][1] + bb.y + x0.y;
            o1.x = c[mt][nt][2] + bb.x + x1.x;
            o1.y = c[mt][nt][3] + bb.y + x1.y;
            *reinterpret_cast<float2*>(out + (size_t)row * DDIM + col) = o0;
            *reinterpret_cast<float2*>(out + (size_t)(row + 8) * DDIM + col) = o1;
        }
    }
}

// ---------------------------------------------------------------------------
// Launch
// inputs: x, gamma, beta, gate_w(unused), w1, b1, w2, b2 ; out fp32
// ---------------------------------------------------------------------------
extern "C" void kernel_launch(void* const* d_in, const int* in_sizes, int n_in,
                              void* d_out, int out_size)
{
    const float* x     = (const float*)d_in[0];
    const float* gamma = (const float*)d_in[1];
    const float* beta  = (const float*)d_in[2];
    const float* w1    = (const float*)d_in[4];
    const float* b1    = (const float*)d_in[5];
    const float* w2    = (const float*)d_in[6];
    const float* b2    = (const float*)d_in[7];
    float* out = (float*)d_out;

    cudaFuncSetAttribute(gemm1_kernel, cudaFuncAttributeMaxDynamicSharedMemorySize, GEMM_SMEM);
    cudaFuncSetAttribute(gemm2_kernel, cudaFuncAttributeMaxDynamicSharedMemorySize, GEMM_SMEM);

    ln_kernel<<<TOK, 256>>>(x, gamma, beta);
    conv_w1_kernel<<<dim3(FDIM / 32, DDIM / 32, 8), dim3(32, 8)>>>(w1);
    conv_w2_kernel<<<dim3(FDIM / 32, DDIM / 32, 8), dim3(32, 8)>>>(w2);
    gemm1_kernel<<<NPAIR * 4 * (FDIM / BN), 256, GEMM_SMEM>>>(b1);
    gemm2_kernel<<<NPAIR * 4 * (DDIM / BN), 256, GEMM_SMEM>>>(b2, x, out);
}